// round 15
// baseline (speedup 1.0000x reference)
#include <cuda_runtime.h>
#include <cuda_fp16.h>
#include <cstdint>

// CapsuleCONV routing — R15: fp16 w in smem (halves the dominant L1
// wavefront traffic, 16->8 per step; half2->float2 cvt lands directly in
// FFMA2 dd-pairs so the w-dup MOVs vanish). R14's 3-step batched softmax
// + integer redux retained. ILP1, z=8, 2 CTAs/SM.
// Launch (repack, nop, nop, main, reduce): executed idx 3 = main.

#define HOUT 15
#define WOUT 15
#define NSPLIT 4
#define NQ 8                              // n per CTA
#define NSITES (32 * 32 * HOUT * WOUT)    // 230400 (b,m,h,w)
#define W_FLOATS (9 * 32 * 512)           // 147456
#define NCOLS 17                          // input cols per CTA

__device__ float g_part[(size_t)NSPLIT * NSITES * 16];   // [part][site][16]
__device__ __half w_packed[W_FLOATS];     // fp16, [chunk][x][m][dd]

#define S_INP_FLOATS (NQ * 3 * NCOLS * 16)       // 6528 floats = 25.5 KB (plain)
#define S_W_BYTES    (2 * 9 * 512 * 2)           // 18432 B fp16 double-buffered
#define SMEM_BYTES   (S_INP_FLOATS * 4 + S_W_BYTES)   // 44544 B

typedef unsigned long long u64;

static __device__ __forceinline__ void cpasync16(uint32_t dst, const void* src) {
    asm volatile("cp.async.cg.shared.global [%0], [%1], 16;" :: "r"(dst), "l"(src));
}
static __device__ __forceinline__ u64 pack2(float lo, float hi) {
    u64 r; asm("mov.b64 %0, {%1, %2};" : "=l"(r) : "f"(lo), "f"(hi)); return r;
}
static __device__ __forceinline__ u64 dup2(float v) { return pack2(v, v); }
static __device__ __forceinline__ void unpack2(u64 v, float& lo, float& hi) {
    asm("mov.b64 {%0, %1}, %2;" : "=f"(lo), "=f"(hi) : "l"(v));
}
static __device__ __forceinline__ u64 fma2(u64 a, u64 b, u64 c) {
    u64 d; asm("fma.rn.f32x2 %0, %1, %2, %3;" : "=l"(d) : "l"(a), "l"(b), "l"(c)); return d;
}
static __device__ __forceinline__ u64 mul2(u64 a, u64 b) {
    u64 d; asm("mul.rn.f32x2 %0, %1, %2;" : "=l"(d) : "l"(a), "l"(b)); return d;
}
static __device__ __forceinline__ u64 add2(u64 a, u64 b) {
    u64 d; asm("add.rn.f32x2 %0, %1, %2;" : "=l"(d) : "l"(a), "l"(b)); return d;
}
static __device__ __forceinline__ float ex2(float x) {
    float r; asm("ex2.approx.f32 %0, %1;" : "=f"(r) : "f"(x)); return r;
}
// Integer warp reduction (sm_80+; fp32 redux is NOT sm_103a — R8 lesson).
static __device__ __forceinline__ uint32_t redux_add_u32(uint32_t v) {
    uint32_t r;
    asm volatile("redux.sync.add.u32 %0, %1, 0xffffffff;" : "=r"(r) : "r"(v));
    return r;
}
static __device__ __forceinline__ void ld16(float* r, const float* p) {
    const float4* g = reinterpret_cast<const float4*>(p);
    float4 t;
    t = g[0]; r[0]  = t.x; r[1]  = t.y; r[2]  = t.z; r[3]  = t.w;
    t = g[1]; r[4]  = t.x; r[5]  = t.y; r[6]  = t.z; r[7]  = t.w;
    t = g[2]; r[8]  = t.x; r[9]  = t.y; r[10] = t.z; r[11] = t.w;
    t = g[3]; r[12] = t.x; r[13] = t.y; r[14] = t.z; r[15] = t.w;
}

// One-time per call: repack w to fp16, [kl][n][x*4+dd][m] -> [chunk][x][m][dd].
__global__ __launch_bounds__(256)
void repack_w(const float* __restrict__ src)
{
    int idx = blockIdx.x * 256 + threadIdx.x;
    if (idx >= W_FLOATS) return;
    int chunk = idx >> 9;
    int r     = idx & 511;
    int x     = r >> 7;
    int m     = (r >> 2) & 31;
    int dd    = r & 3;
    w_packed[idx] = __float2half(src[chunk * 512 + (x * 4 + dd) * 32 + m]);
}

__global__ __launch_bounds__(256, 2)
void capsule_main(const float* __restrict__ input,
                  const float* __restrict__ ncv_g)
{
    extern __shared__ float smem[];
    float*  s_inp = smem;                          // [NQ n][3 k][NCOLS col][16 ch]
    __half* s_w   = reinterpret_cast<__half*>(smem + S_INP_FLOATS);  // [2][9*512]

    const int h     = blockIdx.x;
    const int b     = blockIdx.y;
    const int nh    = blockIdx.z >> 1;       // n quarter: 0..3
    const int whalf = blockIdx.z & 1;        // wpos half
    const int tid   = threadIdx.x;
    const int warp  = tid >> 5;
    const int lane  = tid & 31;              // m
    // whalf 0: wpos 0..7. whalf 1: wpos 8..14, warp 7 duplicates 14 (store guarded).
    const int wpos  = whalf ? (8 + (warp < 7 ? warp : 6)) : warp;
    const bool wr_ok = (whalf == 0) || (warp < 7);
    const int cbase = whalf * 14;            // cols cbase..cbase+16 cover 2*wpos+l
    const int n0    = nh * NQ;

    // ---- input slice: rows 2h+k, cols cbase..cbase+16, plain layout ----
    {
        const float4* gin = reinterpret_cast<const float4*>(input);
        float4* s4 = reinterpret_cast<float4*>(s_inp);
        #pragma unroll 1
        for (int i = tid; i < NQ * 3 * (NCOLS * 4); i += 256) {
            int nk = i / (NCOLS * 4);
            int v  = i - nk * (NCOLS * 4);   // col*4 + quarter
            int n  = nk / 3;
            int k  = nk - n * 3;
            s4[nk * (NCOLS * 4) + v] =
                gin[(((b * 32 + n0 + n) * 32) + (2 * h + k)) * 128 + cbase * 4 + v];
        }
    }

    // ---- packed ncv in registers, dd-pair layout: ncv2[j] = (ch 2j, ch 2j+1) ----
    u64 ncv2[8];
    {
        float t[16];
        ld16(t, ncv_g + ((((size_t)b * 32 + lane) * HOUT + h) * WOUT + wpos) * 16);
        #pragma unroll
        for (int j = 0; j < 8; ++j) ncv2[j] = pack2(t[2 * j], t[2 * j + 1]);
    }

    u64 acc[8];
    #pragma unroll
    for (int j = 0; j < 8; ++j) acc[j] = 0ull;

    const uint32_t swb = (uint32_t)__cvta_generic_to_shared(s_w);

    // preload 9 fp16 w chunks (1 KB each) for ni=0 into buf0. chunk = kl*32+n.
    #pragma unroll 1
    for (int i = tid; i < 576; i += 256) {
        int j = i >> 6, v = i & 63;          // chunk j (0..8), float4 v (0..63)
        cpasync16(swb + (uint32_t)(j * 1024 + v * 16),
                  (const float4*)((const char*)w_packed
                                  + (size_t)(j * 32 + n0) * 1024) + v);
    }
    asm volatile("cp.async.commit_group;");
    asm volatile("cp.async.wait_group 0;" ::: "memory");
    __syncthreads();

    const float QSCALE = 0.25f * 1.4426950408889634f;   // 0.25 * log2(e)
    const float FSCALE = 33554432.0f;                    // 2^25 fixed-point scale
    const int colloc0 = 2 * wpos - cbase;                // local col for l=0

    int buf = 0;
    #pragma unroll 1
    for (int ni = 0; ni < NQ; ++ni) {
        if (ni + 1 < NQ) {
            #pragma unroll 1
            for (int i = tid; i < 576; i += 256) {
                int j = i >> 6, v = i & 63;
                const float4* src = (const float4*)((const char*)w_packed
                    + (size_t)(j * 32 + n0 + ni + 1) * 1024) + v;
                cpasync16(swb + (uint32_t)((buf ^ 1) * 9216 + j * 1024 + v * 16),
                          src);
            }
        }
        asm volatile("cp.async.commit_group;");

        const __half* wbase = s_w + buf * 4608;

        #pragma unroll 1
        for (int kg = 0; kg < 3; ++kg) {
            const float* rowbase = s_inp + (ni * 3 + kg) * (NCOLS * 16);

            u64 V[3][8];
            float es[3];
            uint32_t ei[3];

            // ---- phase 1: votes + qk + exp for l = 0,1,2 (independent) ----
            #pragma unroll
            for (int l = 0; l < 3; ++l) {
                const int s = kg * 3 + l;
                // fp16 w: 4x LDS.64; half2->float2 lands directly as dd-pairs
                u64 wr2[8];
                {
                    const __half* wl = wbase + s * 512 + lane * 4;
                    #pragma unroll
                    for (int x = 0; x < 4; ++x) {
                        uint2 raw = *reinterpret_cast<const uint2*>(wl + x * 128);
                        float2 f01 = __half22float2(
                            *reinterpret_cast<__half2*>(&raw.x));
                        float2 f23 = __half22float2(
                            *reinterpret_cast<__half2*>(&raw.y));
                        wr2[x * 2]     = pack2(f01.x, f01.y);  // (dd0, dd1)
                        wr2[x * 2 + 1] = pack2(f23.x, f23.y);  // (dd2, dd3)
                    }
                }

                float iv[16];
                ld16(iv, rowbase + (colloc0 + l) * 16);

                u64* Vc = V[l];
                #pragma unroll
                for (int a = 0; a < 4; ++a) {
                    u64 d0 = dup2(iv[a * 4 + 0]);
                    u64 va = mul2(d0, wr2[0]);
                    u64 vb = mul2(d0, wr2[1]);
                    u64 d1 = dup2(iv[a * 4 + 1]);
                    va = fma2(d1, wr2[2], va);
                    vb = fma2(d1, wr2[3], vb);
                    u64 d2 = dup2(iv[a * 4 + 2]);
                    va = fma2(d2, wr2[4], va);
                    vb = fma2(d2, wr2[5], vb);
                    u64 d3 = dup2(iv[a * 4 + 3]);
                    va = fma2(d3, wr2[6], va);
                    vb = fma2(d3, wr2[7], vb);
                    Vc[2 * a]     = va;   // channels (a*4+0, a*4+1)
                    Vc[2 * a + 1] = vb;   // channels (a*4+2, a*4+3)
                }

                u64 qa = mul2(Vc[0], ncv2[0]);
                u64 qb = mul2(Vc[1], ncv2[1]);
                qa = fma2(Vc[2], ncv2[2], qa); qb = fma2(Vc[3], ncv2[3], qb);
                qa = fma2(Vc[4], ncv2[4], qa); qb = fma2(Vc[5], ncv2[5], qb);
                qa = fma2(Vc[6], ncv2[6], qa); qb = fma2(Vc[7], ncv2[7], qb);
                float q;
                { float lo, hi; unpack2(add2(qa, qb), lo, hi); q = lo + hi; }

                // e' = 2^(q*QSCALE - 4): bias cancels in e/sum(e); bounds the
                // 2^25 fixed-point 32-lane sum < 2^31.
                float e = ex2(fmaf(q, QSCALE, -4.0f));
                es[l] = e * FSCALE;
                ei[l] = __float2uint_rn(es[l]);
            }

            // ---- phase 2: three independent integer warp reductions ----
            uint32_t s0 = redux_add_u32(ei[0]);
            uint32_t s1 = redux_add_u32(ei[1]);
            uint32_t s2 = redux_add_u32(ei[2]);

            // ---- phase 3: normalize + accumulate ----
            {
                u64 p0 = dup2(__fdividef(es[0], (float)s0));
                u64 p1 = dup2(__fdividef(es[1], (float)s1));
                u64 p2 = dup2(__fdividef(es[2], (float)s2));
                // reference's extra /(sum+1e-10) is a no-op in f32 (sum==1)
                #pragma unroll
                for (int j = 0; j < 8; ++j) {
                    acc[j] = fma2(p0, V[0][j], acc[j]);
                    acc[j] = fma2(p1, V[1][j], acc[j]);
                    acc[j] = fma2(p2, V[2][j], acc[j]);
                }
            }
        }

        asm volatile("cp.async.wait_group 0;" ::: "memory");
        __syncthreads();
        buf ^= 1;
    }

    // ---- store raw partial sums (pre-LN); acc[j] = channels (2j, 2j+1) ----
    if (wr_ok) {
        float a0[16];
        #pragma unroll
        for (int j = 0; j < 8; ++j) unpack2(acc[j], a0[2 * j], a0[2 * j + 1]);
        size_t site = (((size_t)b * 32 + lane) * HOUT + h) * WOUT + wpos;
        float4* g0 = reinterpret_cast<float4*>(g_part + ((size_t)nh * NSITES + site) * 16);
        g0[0] = make_float4(a0[0],  a0[1],  a0[2],  a0[3]);
        g0[1] = make_float4(a0[4],  a0[5],  a0[6],  a0[7]);
        g0[2] = make_float4(a0[8],  a0[9],  a0[10], a0[11]);
        g0[3] = make_float4(a0[12], a0[13], a0[14], a0[15]);
    }
}

__global__ __launch_bounds__(256)
void reduce_ln(float* __restrict__ out,
               const float* __restrict__ gamma,
               const float* __restrict__ beta)
{
    int s = blockIdx.x * 256 + threadIdx.x;
    if (s >= NSITES) return;

    float v[16];
    {
        const float4* p0 = reinterpret_cast<const float4*>(g_part) + (size_t)s * 4;
        #pragma unroll
        for (int i = 0; i < 4; ++i) {
            float4 a = p0[i];
            v[i * 4 + 0] = a.x; v[i * 4 + 1] = a.y;
            v[i * 4 + 2] = a.z; v[i * 4 + 3] = a.w;
        }
    }
    #pragma unroll
    for (int part = 1; part < NSPLIT; ++part) {
        const float4* pp = reinterpret_cast<const float4*>(g_part)
                         + ((size_t)part * NSITES + s) * 4;
        #pragma unroll
        for (int i = 0; i < 4; ++i) {
            float4 a = pp[i];
            v[i * 4 + 0] += a.x; v[i * 4 + 1] += a.y;
            v[i * 4 + 2] += a.z; v[i * 4 + 3] += a.w;
        }
    }

    float mu = 0.f;
    #pragma unroll
    for (int j = 0; j < 16; ++j) mu += v[j];
    mu *= (1.f / 16.f);
    float var = 0.f;
    #pragma unroll
    for (int j = 0; j < 16; ++j) { float d = v[j] - mu; var = fmaf(d, d, var); }
    var *= (1.f / 16.f);
    const float inv = rsqrtf(var + 1e-5f);

    float o[16];
    #pragma unroll
    for (int j = 0; j < 16; ++j)
        o[j] = fmaf((v[j] - mu) * inv, __ldg(gamma + j), __ldg(beta + j));

    float4* gout = reinterpret_cast<float4*>(out + (size_t)s * 16);
    gout[0] = make_float4(o[0],  o[1],  o[2],  o[3]);
    gout[1] = make_float4(o[4],  o[5],  o[6],  o[7]);
    gout[2] = make_float4(o[8],  o[9],  o[10], o[11]);
    gout[3] = make_float4(o[12], o[13], o[14], o[15]);
}

// No-op pads so executed-launch idx 3 = capsule_main (profiled slot).
__global__ void nop_kernel() {}

extern "C" void kernel_launch(void* const* d_in, const int* in_sizes, int n_in,
                              void* d_out, int out_size)
{
    const float* input = (const float*)d_in[0];
    const float* ncv   = (const float*)d_in[1];
    const float* wgt   = (const float*)d_in[2];
    const float* gamma = (const float*)d_in[3];
    const float* beta  = (const float*)d_in[4];
    float* out = (float*)d_out;

    cudaFuncSetAttribute(capsule_main,
                         cudaFuncAttributeMaxDynamicSharedMemorySize, SMEM_BYTES);
    dim3 grid(HOUT, 32, NSPLIT * 2);
    repack_w<<<(W_FLOATS + 255) / 256, 256>>>(wgt);               // pos 0
    nop_kernel<<<1, 1>>>();                                       // pos 1
    nop_kernel<<<1, 1>>>();                                       // pos 2
    capsule_main<<<grid, 256, SMEM_BYTES>>>(input, ncv);          // pos 3 (ncu slot)
    reduce_ln<<<(NSITES + 255) / 256, 256>>>(out, gamma, beta);   // pos 4
}

// round 16
// speedup vs baseline: 1.1267x; 1.1267x over previous
#include <cuda_runtime.h>
#include <cstdint>

// CapsuleCONV routing — R16: R14 (best: fp32 w, 3-step batched softmax,
// integer redux) + wave-count halved (NQ=16, NSPLIT=2 -> 6.5 waves) and
// nop pads stripped (-6.6us). fp16-w reverted (R15: L1 wasn't binding).

#define HOUT 15
#define WOUT 15
#define NSPLIT 2
#define NQ 16                             // n per CTA
#define NSITES (32 * 32 * HOUT * WOUT)    // 230400 (b,m,h,w)
#define W_FLOATS (9 * 32 * 512)           // 147456
#define NCOLS 17                          // input cols per CTA

__device__ float g_part[(size_t)NSPLIT * NSITES * 16];   // [part][site][16]
__device__ float w_packed[W_FLOATS];      // [chunk][x][m][dd]

#define S_INP_FLOATS (NQ * 3 * NCOLS * 16)   // 13056 floats = 51 KB (x-major)
#define S_W_FLOATS   (2 * 9 * 512)           // 9216 floats = 36 KB
#define SMEM_BYTES   ((S_INP_FLOATS + S_W_FLOATS) * 4)   // 89088 B -> 2 CTAs/SM

typedef unsigned long long u64;

static __device__ __forceinline__ void cpasync16(uint32_t dst, const void* src) {
    asm volatile("cp.async.cg.shared.global [%0], [%1], 16;" :: "r"(dst), "l"(src));
}
static __device__ __forceinline__ u64 pack2(float lo, float hi) {
    u64 r; asm("mov.b64 %0, {%1, %2};" : "=l"(r) : "f"(lo), "f"(hi)); return r;
}
static __device__ __forceinline__ u64 dup2(float v) { return pack2(v, v); }
static __device__ __forceinline__ void unpack2(u64 v, float& lo, float& hi) {
    asm("mov.b64 {%0, %1}, %2;" : "=f"(lo), "=f"(hi) : "l"(v));
}
static __device__ __forceinline__ u64 fma2(u64 a, u64 b, u64 c) {
    u64 d; asm("fma.rn.f32x2 %0, %1, %2, %3;" : "=l"(d) : "l"(a), "l"(b), "l"(c)); return d;
}
static __device__ __forceinline__ u64 mul2(u64 a, u64 b) {
    u64 d; asm("mul.rn.f32x2 %0, %1, %2;" : "=l"(d) : "l"(a), "l"(b)); return d;
}
static __device__ __forceinline__ u64 add2(u64 a, u64 b) {
    u64 d; asm("add.rn.f32x2 %0, %1, %2;" : "=l"(d) : "l"(a), "l"(b)); return d;
}
static __device__ __forceinline__ float ex2(float x) {
    float r; asm("ex2.approx.f32 %0, %1;" : "=f"(r) : "f"(x)); return r;
}
// Integer warp reduction (sm_80+; fp32 redux is NOT sm_103a — R8 lesson).
static __device__ __forceinline__ uint32_t redux_add_u32(uint32_t v) {
    uint32_t r;
    asm volatile("redux.sync.add.u32 %0, %1, 0xffffffff;" : "=r"(r) : "r"(v));
    return r;
}
static __device__ __forceinline__ void ld16(float* r, const float* p) {
    const float4* g = reinterpret_cast<const float4*>(p);
    float4 t;
    t = g[0]; r[0]  = t.x; r[1]  = t.y; r[2]  = t.z; r[3]  = t.w;
    t = g[1]; r[4]  = t.x; r[5]  = t.y; r[6]  = t.z; r[7]  = t.w;
    t = g[2]; r[8]  = t.x; r[9]  = t.y; r[10] = t.z; r[11] = t.w;
    t = g[3]; r[12] = t.x; r[13] = t.y; r[14] = t.z; r[15] = t.w;
}

// One-time per call: repack w from [kl][n][x*4+dd][m] to [chunk][x][m][dd].
__global__ __launch_bounds__(256)
void repack_w(const float* __restrict__ src)
{
    int idx = blockIdx.x * 256 + threadIdx.x;
    if (idx >= W_FLOATS) return;
    int chunk = idx >> 9;
    int r     = idx & 511;
    int x     = r >> 7;
    int m     = (r >> 2) & 31;
    int dd    = r & 3;
    w_packed[idx] = src[chunk * 512 + (x * 4 + dd) * 32 + m];
}

__global__ __launch_bounds__(256, 2)
void capsule_main(const float* __restrict__ input,
                  const float* __restrict__ ncv_g)
{
    extern __shared__ float smem[];
    float* s_inp = smem;                    // [NQ n][3 k][NCOLS col][16 ch x-major]
    float* s_w   = smem + S_INP_FLOATS;     // [2][9*512] packed [x][m][dd]

    const int h     = blockIdx.x;
    const int b     = blockIdx.y;
    const int nh    = blockIdx.z >> 1;       // n half: 0..1
    const int whalf = blockIdx.z & 1;        // wpos half
    const int tid   = threadIdx.x;
    const int warp  = tid >> 5;
    const int lane  = tid & 31;              // m
    // whalf 0: wpos 0..7. whalf 1: wpos 8..14, warp 7 duplicates 14 (store guarded).
    const int wpos  = whalf ? (8 + (warp < 7 ? warp : 6)) : warp;
    const bool wr_ok = (whalf == 0) || (warp < 7);
    const int cbase = whalf * 14;            // cols cbase..cbase+16 cover 2*wpos+l
    const int n0    = nh * NQ;

    // ---- input slice: rows 2h+k, cols cbase..cbase+16, n0..n0+NQ-1.
    //      Coalesced gmem float4 reads; smem stored x-major (ch x*4+a). ----
    {
        const float4* gin = reinterpret_cast<const float4*>(input);
        #pragma unroll 1
        for (int i = tid; i < NQ * 3 * (NCOLS * 4); i += 256) {
            int nk = i / (NCOLS * 4);
            int v  = i - nk * (NCOLS * 4);   // col*4 + a
            int n  = nk / 3;
            int k  = nk - n * 3;
            float4 t = gin[(((b * 32 + n0 + n) * 32) + (2 * h + k)) * 128
                           + cbase * 4 + v];
            int col = v >> 2, a = v & 3;
            float* dst = s_inp + nk * (NCOLS * 16) + col * 16 + a;  // slot x*4+a
            dst[0]  = t.x;   // x=0
            dst[4]  = t.y;   // x=1
            dst[8]  = t.z;   // x=2
            dst[12] = t.w;   // x=3
        }
    }

    // ---- packed ncv in registers, a-pair layout [p*4+dd] ----
    u64 ncv2[8];
    {
        float t[16];
        ld16(t, ncv_g + ((((size_t)b * 32 + lane) * HOUT + h) * WOUT + wpos) * 16);
        #pragma unroll
        for (int p = 0; p < 2; ++p)
            #pragma unroll
            for (int dd = 0; dd < 4; ++dd)
                ncv2[p * 4 + dd] = pack2(t[p * 8 + dd], t[p * 8 + 4 + dd]);
    }

    u64 acc[8];
    #pragma unroll
    for (int j = 0; j < 8; ++j) acc[j] = 0ull;

    const uint32_t swb = (uint32_t)__cvta_generic_to_shared(s_w);

    // preload all 9 packed w chunks for ni=0 into buf0. chunk id = kl*32 + n.
    #pragma unroll 1
    for (int i = tid; i < 1152; i += 256) {
        int j = i >> 7, v = i & 127;
        cpasync16(swb + (uint32_t)(j * 512 + v * 4) * 4u,
                  (const float4*)(w_packed + (size_t)(j * 32 + n0) * 512) + v);
    }
    asm volatile("cp.async.commit_group;");
    asm volatile("cp.async.wait_group 0;" ::: "memory");
    __syncthreads();

    const float QSCALE = 0.25f * 1.4426950408889634f;   // 0.25 * log2(e)
    const float FSCALE = 33554432.0f;                    // 2^25 fixed-point scale
    const int colloc0 = 2 * wpos - cbase;                // local col for l=0

    int buf = 0;
    #pragma unroll 1
    for (int ni = 0; ni < NQ; ++ni) {
        if (ni + 1 < NQ) {
            #pragma unroll 1
            for (int i = tid; i < 1152; i += 256) {
                int j = i >> 7, v = i & 127;
                const float4* src = (const float4*)(
                    w_packed + (size_t)(j * 32 + n0 + ni + 1) * 512) + v;
                cpasync16(swb + (uint32_t)((buf ^ 1) * 4608 + j * 512 + v * 4) * 4u,
                          src);
            }
        }
        asm volatile("cp.async.commit_group;");

        const float4* wv = reinterpret_cast<const float4*>(s_w + buf * 4608);

        #pragma unroll 1
        for (int kg = 0; kg < 3; ++kg) {
            const float* rowbase = s_inp + (ni * 3 + kg) * (NCOLS * 16);

            u64 V[3][8];
            float es[3];
            uint32_t ei[3];

            // ---- phase 1: votes + qk + exp for l = 0,1,2 (independent) ----
            #pragma unroll
            for (int l = 0; l < 3; ++l) {
                const int s = kg * 3 + l;
                float4 wf0 = wv[s * 128 +       lane];
                float4 wf1 = wv[s * 128 + 32  + lane];
                float4 wf2 = wv[s * 128 + 64  + lane];
                float4 wf3 = wv[s * 128 + 96  + lane];
                const ulonglong2* ip = reinterpret_cast<const ulonglong2*>(
                    rowbase + (colloc0 + l) * 16);
                ulonglong2 i0 = ip[0], i1 = ip[1], i2 = ip[2], i3 = ip[3];

                u64* Vc = V[l];
                {
                    u64 w0d = dup2(wf0.x), w1d = dup2(wf0.y),
                        w2d = dup2(wf0.z), w3d = dup2(wf0.w);
                    Vc[0] = mul2(i0.x, w0d); Vc[1] = mul2(i0.x, w1d);
                    Vc[2] = mul2(i0.x, w2d); Vc[3] = mul2(i0.x, w3d);
                    Vc[4] = mul2(i0.y, w0d); Vc[5] = mul2(i0.y, w1d);
                    Vc[6] = mul2(i0.y, w2d); Vc[7] = mul2(i0.y, w3d);
                }
                {
                    u64 w0d = dup2(wf1.x), w1d = dup2(wf1.y),
                        w2d = dup2(wf1.z), w3d = dup2(wf1.w);
                    Vc[0] = fma2(i1.x, w0d, Vc[0]); Vc[1] = fma2(i1.x, w1d, Vc[1]);
                    Vc[2] = fma2(i1.x, w2d, Vc[2]); Vc[3] = fma2(i1.x, w3d, Vc[3]);
                    Vc[4] = fma2(i1.y, w0d, Vc[4]); Vc[5] = fma2(i1.y, w1d, Vc[5]);
                    Vc[6] = fma2(i1.y, w2d, Vc[6]); Vc[7] = fma2(i1.y, w3d, Vc[7]);
                }
                {
                    u64 w0d = dup2(wf2.x), w1d = dup2(wf2.y),
                        w2d = dup2(wf2.z), w3d = dup2(wf2.w);
                    Vc[0] = fma2(i2.x, w0d, Vc[0]); Vc[1] = fma2(i2.x, w1d, Vc[1]);
                    Vc[2] = fma2(i2.x, w2d, Vc[2]); Vc[3] = fma2(i2.x, w3d, Vc[3]);
                    Vc[4] = fma2(i2.y, w0d, Vc[4]); Vc[5] = fma2(i2.y, w1d, Vc[5]);
                    Vc[6] = fma2(i2.y, w2d, Vc[6]); Vc[7] = fma2(i2.y, w3d, Vc[7]);
                }
                {
                    u64 w0d = dup2(wf3.x), w1d = dup2(wf3.y),
                        w2d = dup2(wf3.z), w3d = dup2(wf3.w);
                    Vc[0] = fma2(i3.x, w0d, Vc[0]); Vc[1] = fma2(i3.x, w1d, Vc[1]);
                    Vc[2] = fma2(i3.x, w2d, Vc[2]); Vc[3] = fma2(i3.x, w3d, Vc[3]);
                    Vc[4] = fma2(i3.y, w0d, Vc[4]); Vc[5] = fma2(i3.y, w1d, Vc[5]);
                    Vc[6] = fma2(i3.y, w2d, Vc[6]); Vc[7] = fma2(i3.y, w3d, Vc[7]);
                }

                u64 qa = mul2(Vc[0], ncv2[0]);
                u64 qb = mul2(Vc[1], ncv2[1]);
                qa = fma2(Vc[2], ncv2[2], qa); qb = fma2(Vc[3], ncv2[3], qb);
                qa = fma2(Vc[4], ncv2[4], qa); qb = fma2(Vc[5], ncv2[5], qb);
                qa = fma2(Vc[6], ncv2[6], qa); qb = fma2(Vc[7], ncv2[7], qb);
                float q;
                { float lo, hi; unpack2(add2(qa, qb), lo, hi); q = lo + hi; }

                // e' = 2^(q*QSCALE - 4): constant bias cancels in e/sum(e);
                // bounds e' <= ~1 so the 2^25 fixed-point 32-lane sum < 2^31.
                float e = ex2(fmaf(q, QSCALE, -4.0f));
                es[l] = e * FSCALE;
                ei[l] = __float2uint_rn(es[l]);
            }

            // ---- phase 2: three independent integer warp reductions ----
            uint32_t s0 = redux_add_u32(ei[0]);
            uint32_t s1 = redux_add_u32(ei[1]);
            uint32_t s2 = redux_add_u32(ei[2]);

            // ---- phase 3: normalize + accumulate (independent per l) ----
            {
                u64 p0 = dup2(__fdividef(es[0], (float)s0));
                u64 p1 = dup2(__fdividef(es[1], (float)s1));
                u64 p2 = dup2(__fdividef(es[2], (float)s2));
                // reference's extra /(sum+1e-10) is a no-op in f32 (sum==1)
                #pragma unroll
                for (int j = 0; j < 8; ++j) {
                    acc[j] = fma2(p0, V[0][j], acc[j]);
                    acc[j] = fma2(p1, V[1][j], acc[j]);
                    acc[j] = fma2(p2, V[2][j], acc[j]);
                }
            }
        }

        asm volatile("cp.async.wait_group 0;" ::: "memory");
        __syncthreads();
        buf ^= 1;
    }

    // ---- store raw partial sums (pre-LN); unmap a-pair packing ----
    if (wr_ok) {
        float a0[16];
        #pragma unroll
        for (int j = 0; j < 8; ++j) {
            int p = j >> 2, dd = j & 3;
            unpack2(acc[j], a0[p * 8 + dd], a0[p * 8 + 4 + dd]);
        }
        size_t site = (((size_t)b * 32 + lane) * HOUT + h) * WOUT + wpos;
        float4* g0 = reinterpret_cast<float4*>(g_part + ((size_t)nh * NSITES + site) * 16);
        g0[0] = make_float4(a0[0],  a0[1],  a0[2],  a0[3]);
        g0[1] = make_float4(a0[4],  a0[5],  a0[6],  a0[7]);
        g0[2] = make_float4(a0[8],  a0[9],  a0[10], a0[11]);
        g0[3] = make_float4(a0[12], a0[13], a0[14], a0[15]);
    }
}

__global__ __launch_bounds__(256)
void reduce_ln(float* __restrict__ out,
               const float* __restrict__ gamma,
               const float* __restrict__ beta)
{
    int s = blockIdx.x * 256 + threadIdx.x;
    if (s >= NSITES) return;

    float v[16];
    {
        const float4* p0 = reinterpret_cast<const float4*>(g_part) + (size_t)s * 4;
        #pragma unroll
        for (int i = 0; i < 4; ++i) {
            float4 a = p0[i];
            v[i * 4 + 0] = a.x; v[i * 4 + 1] = a.y;
            v[i * 4 + 2] = a.z; v[i * 4 + 3] = a.w;
        }
    }
    #pragma unroll
    for (int part = 1; part < NSPLIT; ++part) {
        const float4* pp = reinterpret_cast<const float4*>(g_part)
                         + ((size_t)part * NSITES + s) * 4;
        #pragma unroll
        for (int i = 0; i < 4; ++i) {
            float4 a = pp[i];
            v[i * 4 + 0] += a.x; v[i * 4 + 1] += a.y;
            v[i * 4 + 2] += a.z; v[i * 4 + 3] += a.w;
        }
    }

    float mu = 0.f;
    #pragma unroll
    for (int j = 0; j < 16; ++j) mu += v[j];
    mu *= (1.f / 16.f);
    float var = 0.f;
    #pragma unroll
    for (int j = 0; j < 16; ++j) { float d = v[j] - mu; var = fmaf(d, d, var); }
    var *= (1.f / 16.f);
    const float inv = rsqrtf(var + 1e-5f);

    float o[16];
    #pragma unroll
    for (int j = 0; j < 16; ++j)
        o[j] = fmaf((v[j] - mu) * inv, __ldg(gamma + j), __ldg(beta + j));

    float4* gout = reinterpret_cast<float4*>(out + (size_t)s * 16);
    gout[0] = make_float4(o[0],  o[1],  o[2],  o[3]);
    gout[1] = make_float4(o[4],  o[5],  o[6],  o[7]);
    gout[2] = make_float4(o[8],  o[9],  o[10], o[11]);
    gout[3] = make_float4(o[12], o[13], o[14], o[15]);
}

extern "C" void kernel_launch(void* const* d_in, const int* in_sizes, int n_in,
                              void* d_out, int out_size)
{
    const float* input = (const float*)d_in[0];
    const float* ncv   = (const float*)d_in[1];
    const float* wgt   = (const float*)d_in[2];
    const float* gamma = (const float*)d_in[3];
    const float* beta  = (const float*)d_in[4];
    float* out = (float*)d_out;

    cudaFuncSetAttribute(capsule_main,
                         cudaFuncAttributeMaxDynamicSharedMemorySize, SMEM_BYTES);
    dim3 grid(HOUT, 32, NSPLIT * 2);
    repack_w<<<(W_FLOATS + 255) / 256, 256>>>(wgt);
    capsule_main<<<grid, 256, SMEM_BYTES>>>(input, ncv);
    reduce_ln<<<(NSITES + 255) / 256, 256>>>(out, gamma, beta);
}

// round 17
// speedup vs baseline: 1.1647x; 1.0337x over previous
#include <cuda_runtime.h>
#include <cstdint>

// CapsuleCONV routing — R17: R16 + kg loop fully unrolled. The three
// kg-groups per ni are independent (no barriers between them); unrolling
// removes the artificial scheduling fence so ptxas overlaps group g's
// redux/divide tail with group g+1's LDS + vote FMA burst.

#define HOUT 15
#define WOUT 15
#define NSPLIT 2
#define NQ 16                             // n per CTA
#define NSITES (32 * 32 * HOUT * WOUT)    // 230400 (b,m,h,w)
#define W_FLOATS (9 * 32 * 512)           // 147456
#define NCOLS 17                          // input cols per CTA

__device__ float g_part[(size_t)NSPLIT * NSITES * 16];   // [part][site][16]
__device__ float w_packed[W_FLOATS];      // [chunk][x][m][dd]

#define S_INP_FLOATS (NQ * 3 * NCOLS * 16)   // 13056 floats = 51 KB (x-major)
#define S_W_FLOATS   (2 * 9 * 512)           // 9216 floats = 36 KB
#define SMEM_BYTES   ((S_INP_FLOATS + S_W_FLOATS) * 4)   // 89088 B -> 2 CTAs/SM

typedef unsigned long long u64;

static __device__ __forceinline__ void cpasync16(uint32_t dst, const void* src) {
    asm volatile("cp.async.cg.shared.global [%0], [%1], 16;" :: "r"(dst), "l"(src));
}
static __device__ __forceinline__ u64 pack2(float lo, float hi) {
    u64 r; asm("mov.b64 %0, {%1, %2};" : "=l"(r) : "f"(lo), "f"(hi)); return r;
}
static __device__ __forceinline__ u64 dup2(float v) { return pack2(v, v); }
static __device__ __forceinline__ void unpack2(u64 v, float& lo, float& hi) {
    asm("mov.b64 {%0, %1}, %2;" : "=f"(lo), "=f"(hi) : "l"(v));
}
static __device__ __forceinline__ u64 fma2(u64 a, u64 b, u64 c) {
    u64 d; asm("fma.rn.f32x2 %0, %1, %2, %3;" : "=l"(d) : "l"(a), "l"(b), "l"(c)); return d;
}
static __device__ __forceinline__ u64 mul2(u64 a, u64 b) {
    u64 d; asm("mul.rn.f32x2 %0, %1, %2;" : "=l"(d) : "l"(a), "l"(b)); return d;
}
static __device__ __forceinline__ u64 add2(u64 a, u64 b) {
    u64 d; asm("add.rn.f32x2 %0, %1, %2;" : "=l"(d) : "l"(a), "l"(b)); return d;
}
static __device__ __forceinline__ float ex2(float x) {
    float r; asm("ex2.approx.f32 %0, %1;" : "=f"(r) : "f"(x)); return r;
}
// Integer warp reduction (sm_80+; fp32 redux is NOT sm_103a — R8 lesson).
static __device__ __forceinline__ uint32_t redux_add_u32(uint32_t v) {
    uint32_t r;
    asm volatile("redux.sync.add.u32 %0, %1, 0xffffffff;" : "=r"(r) : "r"(v));
    return r;
}
static __device__ __forceinline__ void ld16(float* r, const float* p) {
    const float4* g = reinterpret_cast<const float4*>(p);
    float4 t;
    t = g[0]; r[0]  = t.x; r[1]  = t.y; r[2]  = t.z; r[3]  = t.w;
    t = g[1]; r[4]  = t.x; r[5]  = t.y; r[6]  = t.z; r[7]  = t.w;
    t = g[2]; r[8]  = t.x; r[9]  = t.y; r[10] = t.z; r[11] = t.w;
    t = g[3]; r[12] = t.x; r[13] = t.y; r[14] = t.z; r[15] = t.w;
}

// One-time per call: repack w from [kl][n][x*4+dd][m] to [chunk][x][m][dd].
__global__ __launch_bounds__(256)
void repack_w(const float* __restrict__ src)
{
    int idx = blockIdx.x * 256 + threadIdx.x;
    if (idx >= W_FLOATS) return;
    int chunk = idx >> 9;
    int r     = idx & 511;
    int x     = r >> 7;
    int m     = (r >> 2) & 31;
    int dd    = r & 3;
    w_packed[idx] = src[chunk * 512 + (x * 4 + dd) * 32 + m];
}

__global__ __launch_bounds__(256, 2)
void capsule_main(const float* __restrict__ input,
                  const float* __restrict__ ncv_g)
{
    extern __shared__ float smem[];
    float* s_inp = smem;                    // [NQ n][3 k][NCOLS col][16 ch x-major]
    float* s_w   = smem + S_INP_FLOATS;     // [2][9*512] packed [x][m][dd]

    const int h     = blockIdx.x;
    const int b     = blockIdx.y;
    const int nh    = blockIdx.z >> 1;       // n half: 0..1
    const int whalf = blockIdx.z & 1;        // wpos half
    const int tid   = threadIdx.x;
    const int warp  = tid >> 5;
    const int lane  = tid & 31;              // m
    // whalf 0: wpos 0..7. whalf 1: wpos 8..14, warp 7 duplicates 14 (store guarded).
    const int wpos  = whalf ? (8 + (warp < 7 ? warp : 6)) : warp;
    const bool wr_ok = (whalf == 0) || (warp < 7);
    const int cbase = whalf * 14;            // cols cbase..cbase+16 cover 2*wpos+l
    const int n0    = nh * NQ;

    // ---- input slice: rows 2h+k, cols cbase..cbase+16, n0..n0+NQ-1.
    //      Coalesced gmem float4 reads; smem stored x-major (ch x*4+a). ----
    {
        const float4* gin = reinterpret_cast<const float4*>(input);
        #pragma unroll 1
        for (int i = tid; i < NQ * 3 * (NCOLS * 4); i += 256) {
            int nk = i / (NCOLS * 4);
            int v  = i - nk * (NCOLS * 4);   // col*4 + a
            int n  = nk / 3;
            int k  = nk - n * 3;
            float4 t = gin[(((b * 32 + n0 + n) * 32) + (2 * h + k)) * 128
                           + cbase * 4 + v];
            int col = v >> 2, a = v & 3;
            float* dst = s_inp + nk * (NCOLS * 16) + col * 16 + a;  // slot x*4+a
            dst[0]  = t.x;   // x=0
            dst[4]  = t.y;   // x=1
            dst[8]  = t.z;   // x=2
            dst[12] = t.w;   // x=3
        }
    }

    // ---- packed ncv in registers, a-pair layout [p*4+dd] ----
    u64 ncv2[8];
    {
        float t[16];
        ld16(t, ncv_g + ((((size_t)b * 32 + lane) * HOUT + h) * WOUT + wpos) * 16);
        #pragma unroll
        for (int p = 0; p < 2; ++p)
            #pragma unroll
            for (int dd = 0; dd < 4; ++dd)
                ncv2[p * 4 + dd] = pack2(t[p * 8 + dd], t[p * 8 + 4 + dd]);
    }

    u64 acc[8];
    #pragma unroll
    for (int j = 0; j < 8; ++j) acc[j] = 0ull;

    const uint32_t swb = (uint32_t)__cvta_generic_to_shared(s_w);

    // preload all 9 packed w chunks for ni=0 into buf0. chunk id = kl*32 + n.
    #pragma unroll 1
    for (int i = tid; i < 1152; i += 256) {
        int j = i >> 7, v = i & 127;
        cpasync16(swb + (uint32_t)(j * 512 + v * 4) * 4u,
                  (const float4*)(w_packed + (size_t)(j * 32 + n0) * 512) + v);
    }
    asm volatile("cp.async.commit_group;");
    asm volatile("cp.async.wait_group 0;" ::: "memory");
    __syncthreads();

    const float QSCALE = 0.25f * 1.4426950408889634f;   // 0.25 * log2(e)
    const float FSCALE = 33554432.0f;                    // 2^25 fixed-point scale
    const int colloc0 = 2 * wpos - cbase;                // local col for l=0

    int buf = 0;
    #pragma unroll 1
    for (int ni = 0; ni < NQ; ++ni) {
        if (ni + 1 < NQ) {
            #pragma unroll 1
            for (int i = tid; i < 1152; i += 256) {
                int j = i >> 7, v = i & 127;
                const float4* src = (const float4*)(
                    w_packed + (size_t)(j * 32 + n0 + ni + 1) * 512) + v;
                cpasync16(swb + (uint32_t)((buf ^ 1) * 4608 + j * 512 + v * 4) * 4u,
                          src);
            }
        }
        asm volatile("cp.async.commit_group;");

        const float4* wv = reinterpret_cast<const float4*>(s_w + buf * 4608);

        // kg fully unrolled: the 3 groups are independent, letting ptxas
        // overlap group g's redux/divide tail with group g+1's LDS+FMA burst.
        #pragma unroll
        for (int kg = 0; kg < 3; ++kg) {
            const float* rowbase = s_inp + (ni * 3 + kg) * (NCOLS * 16);

            u64 V[3][8];
            float es[3];
            uint32_t ei[3];

            // ---- phase 1: votes + qk + exp for l = 0,1,2 (independent) ----
            #pragma unroll
            for (int l = 0; l < 3; ++l) {
                const int s = kg * 3 + l;
                float4 wf0 = wv[s * 128 +       lane];
                float4 wf1 = wv[s * 128 + 32  + lane];
                float4 wf2 = wv[s * 128 + 64  + lane];
                float4 wf3 = wv[s * 128 + 96  + lane];
                const ulonglong2* ip = reinterpret_cast<const ulonglong2*>(
                    rowbase + (colloc0 + l) * 16);
                ulonglong2 i0 = ip[0], i1 = ip[1], i2 = ip[2], i3 = ip[3];

                u64* Vc = V[l];
                {
                    u64 w0d = dup2(wf0.x), w1d = dup2(wf0.y),
                        w2d = dup2(wf0.z), w3d = dup2(wf0.w);
                    Vc[0] = mul2(i0.x, w0d); Vc[1] = mul2(i0.x, w1d);
                    Vc[2] = mul2(i0.x, w2d); Vc[3] = mul2(i0.x, w3d);
                    Vc[4] = mul2(i0.y, w0d); Vc[5] = mul2(i0.y, w1d);
                    Vc[6] = mul2(i0.y, w2d); Vc[7] = mul2(i0.y, w3d);
                }
                {
                    u64 w0d = dup2(wf1.x), w1d = dup2(wf1.y),
                        w2d = dup2(wf1.z), w3d = dup2(wf1.w);
                    Vc[0] = fma2(i1.x, w0d, Vc[0]); Vc[1] = fma2(i1.x, w1d, Vc[1]);
                    Vc[2] = fma2(i1.x, w2d, Vc[2]); Vc[3] = fma2(i1.x, w3d, Vc[3]);
                    Vc[4] = fma2(i1.y, w0d, Vc[4]); Vc[5] = fma2(i1.y, w1d, Vc[5]);
                    Vc[6] = fma2(i1.y, w2d, Vc[6]); Vc[7] = fma2(i1.y, w3d, Vc[7]);
                }
                {
                    u64 w0d = dup2(wf2.x), w1d = dup2(wf2.y),
                        w2d = dup2(wf2.z), w3d = dup2(wf2.w);
                    Vc[0] = fma2(i2.x, w0d, Vc[0]); Vc[1] = fma2(i2.x, w1d, Vc[1]);
                    Vc[2] = fma2(i2.x, w2d, Vc[2]); Vc[3] = fma2(i2.x, w3d, Vc[3]);
                    Vc[4] = fma2(i2.y, w0d, Vc[4]); Vc[5] = fma2(i2.y, w1d, Vc[5]);
                    Vc[6] = fma2(i2.y, w2d, Vc[6]); Vc[7] = fma2(i2.y, w3d, Vc[7]);
                }
                {
                    u64 w0d = dup2(wf3.x), w1d = dup2(wf3.y),
                        w2d = dup2(wf3.z), w3d = dup2(wf3.w);
                    Vc[0] = fma2(i3.x, w0d, Vc[0]); Vc[1] = fma2(i3.x, w1d, Vc[1]);
                    Vc[2] = fma2(i3.x, w2d, Vc[2]); Vc[3] = fma2(i3.x, w3d, Vc[3]);
                    Vc[4] = fma2(i3.y, w0d, Vc[4]); Vc[5] = fma2(i3.y, w1d, Vc[5]);
                    Vc[6] = fma2(i3.y, w2d, Vc[6]); Vc[7] = fma2(i3.y, w3d, Vc[7]);
                }

                u64 qa = mul2(Vc[0], ncv2[0]);
                u64 qb = mul2(Vc[1], ncv2[1]);
                qa = fma2(Vc[2], ncv2[2], qa); qb = fma2(Vc[3], ncv2[3], qb);
                qa = fma2(Vc[4], ncv2[4], qa); qb = fma2(Vc[5], ncv2[5], qb);
                qa = fma2(Vc[6], ncv2[6], qa); qb = fma2(Vc[7], ncv2[7], qb);
                float q;
                { float lo, hi; unpack2(add2(qa, qb), lo, hi); q = lo + hi; }

                // e' = 2^(q*QSCALE - 4): constant bias cancels in e/sum(e);
                // bounds e' <= ~1 so the 2^25 fixed-point 32-lane sum < 2^31.
                float e = ex2(fmaf(q, QSCALE, -4.0f));
                es[l] = e * FSCALE;
                ei[l] = __float2uint_rn(es[l]);
            }

            // ---- phase 2: three independent integer warp reductions ----
            uint32_t s0 = redux_add_u32(ei[0]);
            uint32_t s1 = redux_add_u32(ei[1]);
            uint32_t s2 = redux_add_u32(ei[2]);

            // ---- phase 3: normalize + accumulate (independent per l) ----
            {
                u64 p0 = dup2(__fdividef(es[0], (float)s0));
                u64 p1 = dup2(__fdividef(es[1], (float)s1));
                u64 p2 = dup2(__fdividef(es[2], (float)s2));
                // reference's extra /(sum+1e-10) is a no-op in f32 (sum==1)
                #pragma unroll
                for (int j = 0; j < 8; ++j) {
                    acc[j] = fma2(p0, V[0][j], acc[j]);
                    acc[j] = fma2(p1, V[1][j], acc[j]);
                    acc[j] = fma2(p2, V[2][j], acc[j]);
                }
            }
        }

        asm volatile("cp.async.wait_group 0;" ::: "memory");
        __syncthreads();
        buf ^= 1;
    }

    // ---- store raw partial sums (pre-LN); unmap a-pair packing ----
    if (wr_ok) {
        float a0[16];
        #pragma unroll
        for (int j = 0; j < 8; ++j) {
            int p = j >> 2, dd = j & 3;
            unpack2(acc[j], a0[p * 8 + dd], a0[p * 8 + 4 + dd]);
        }
        size_t site = (((size_t)b * 32 + lane) * HOUT + h) * WOUT + wpos;
        float4* g0 = reinterpret_cast<float4*>(g_part + ((size_t)nh * NSITES + site) * 16);
        g0[0] = make_float4(a0[0],  a0[1],  a0[2],  a0[3]);
        g0[1] = make_float4(a0[4],  a0[5],  a0[6],  a0[7]);
        g0[2] = make_float4(a0[8],  a0[9],  a0[10], a0[11]);
        g0[3] = make_float4(a0[12], a0[13], a0[14], a0[15]);
    }
}

__global__ __launch_bounds__(256)
void reduce_ln(float* __restrict__ out,
               const float* __restrict__ gamma,
               const float* __restrict__ beta)
{
    int s = blockIdx.x * 256 + threadIdx.x;
    if (s >= NSITES) return;

    float v[16];
    {
        const float4* p0 = reinterpret_cast<const float4*>(g_part) + (size_t)s * 4;
        #pragma unroll
        for (int i = 0; i < 4; ++i) {
            float4 a = p0[i];
            v[i * 4 + 0] = a.x; v[i * 4 + 1] = a.y;
            v[i * 4 + 2] = a.z; v[i * 4 + 3] = a.w;
        }
    }
    #pragma unroll
    for (int part = 1; part < NSPLIT; ++part) {
        const float4* pp = reinterpret_cast<const float4*>(g_part)
                         + ((size_t)part * NSITES + s) * 4;
        #pragma unroll
        for (int i = 0; i < 4; ++i) {
            float4 a = pp[i];
            v[i * 4 + 0] += a.x; v[i * 4 + 1] += a.y;
            v[i * 4 + 2] += a.z; v[i * 4 + 3] += a.w;
        }
    }

    float mu = 0.f;
    #pragma unroll
    for (int j = 0; j < 16; ++j) mu += v[j];
    mu *= (1.f / 16.f);
    float var = 0.f;
    #pragma unroll
    for (int j = 0; j < 16; ++j) { float d = v[j] - mu; var = fmaf(d, d, var); }
    var *= (1.f / 16.f);
    const float inv = rsqrtf(var + 1e-5f);

    float o[16];
    #pragma unroll
    for (int j = 0; j < 16; ++j)
        o[j] = fmaf((v[j] - mu) * inv, __ldg(gamma + j), __ldg(beta + j));

    float4* gout = reinterpret_cast<float4*>(out + (size_t)s * 16);
    gout[0] = make_float4(o[0],  o[1],  o[2],  o[3]);
    gout[1] = make_float4(o[4],  o[5],  o[6],  o[7]);
    gout[2] = make_float4(o[8],  o[9],  o[10], o[11]);
    gout[3] = make_float4(o[12], o[13], o[14], o[15]);
}

extern "C" void kernel_launch(void* const* d_in, const int* in_sizes, int n_in,
                              void* d_out, int out_size)
{
    const float* input = (const float*)d_in[0];
    const float* ncv   = (const float*)d_in[1];
    const float* wgt   = (const float*)d_in[2];
    const float* gamma = (const float*)d_in[3];
    const float* beta  = (const float*)d_in[4];
    float* out = (float*)d_out;

    cudaFuncSetAttribute(capsule_main,
                         cudaFuncAttributeMaxDynamicSharedMemorySize, SMEM_BYTES);
    dim3 grid(HOUT, 32, NSPLIT * 2);
    repack_w<<<(W_FLOATS + 255) / 256, 256>>>(wgt);
    capsule_main<<<grid, 256, SMEM_BYTES>>>(input, ncv);
    reduce_ln<<<(NSITES + 255) / 256, 256>>>(out, gamma, beta);
}